// round 14
// baseline (speedup 1.0000x reference)
#include <cuda_runtime.h>
#include <cuda_bf16.h>
#include <mma.h>
#include <math.h>
#include <stdint.h>

using namespace nvcuda;

#define POSN  65536
#define SCALE 0.35355339059327373f

// Scratch (device globals; allocation-free rule)
__device__ float g_G  [4194304];            // gelu out, flat: [t*64+c] == CHW [c][pos]
__device__ float g_QKV[48 * 65536];         // [j][pos]
__device__ __nv_bfloat16 g_Pb[4194304];     // proj out bf16, flat dual-view

// pack (lo=a, hi=b) into bf16x2
__device__ __forceinline__ uint32_t pk(float a, float b) {
    uint32_t r;
    asm("cvt.rn.bf16x2.f32 %0, %2, %1;" : "=r"(r) : "f"(a), "f"(b));
    return r;
}
__device__ __forceinline__ uint2 pk4(float4 v) {
    uint2 r; r.x = pk(v.x, v.y); r.y = pk(v.z, v.w); return r;
}
__device__ __forceinline__ uint4 pk8(const float* s) {
    float4 a = *(const float4*)s, b = *(const float4*)(s + 4);
    uint4 w;
    w.x = pk(a.x, a.y); w.y = pk(a.z, a.w);
    w.z = pk(b.x, b.y); w.w = pk(b.z, b.w);
    return w;
}
__device__ __forceinline__ float gelu_exact(float h) {
    return 0.5f * h * (1.0f + erff(h * 0.70710678118654752f));
}

typedef wmma::fragment<wmma::matrix_a, 16, 16, 16, __nv_bfloat16, wmma::row_major> FragA;
typedef wmma::fragment<wmma::matrix_b, 16, 16, 16, __nv_bfloat16, wmma::col_major> FragB;
typedef wmma::fragment<wmma::accumulator, 16, 16, 16, float> FragC;

#define LDA 80   // bf16 A buffers: 160B rows
#define LDC 72   // fp32 C buffer

// ---------------------------------------------------------------------------
// K1: fc1 (768->64, bf16 wmma, reg-prefetch double-buffered) + 8x conv64
//     (bf16 wmma, SMEM ping-pong, weights prefetched) + L5->L7 skip + GELU.
// 128 tokens/CTA, 4 warps, 512 CTAs.  (unchanged)
// ---------------------------------------------------------------------------
__global__ __launch_bounds__(128) void k1_mma(
    const float* __restrict__ x, const float* __restrict__ fc1_w,
    const float* __restrict__ fc1_b, const float* __restrict__ conv_w,
    const float* __restrict__ conv_b)
{
    extern __shared__ char sm[];
    float*         Cf  = (float*)sm;
    __nv_bfloat16* A0  = (__nv_bfloat16*)(sm + 36864);
    __nv_bfloat16* A1  = (__nv_bfloat16*)(sm + 57344);
    __nv_bfloat16* Bb0 = (__nv_bfloat16*)(sm + 77824);
    __nv_bfloat16* Bb1 = (__nv_bfloat16*)(sm + 86016);
    float* biasF = (float*)(sm + 94208);
    float* biasC = biasF + 64;

    const int tid = threadIdx.x;
    const int wid = tid >> 5;
    const int t0  = blockIdx.x * 128;
    const int m0  = wid * 32;

    if (tid < 64) biasF[tid] = fc1_b[tid];
    for (int i = tid; i < 512; i += 128) biasC[i] = conv_b[i];

    const int xr_row = tid >> 4;
    const int xr_c4  = tid & 15;
    const float* xbase = x + (size_t)t0 * 768;

    uint2 xp[16];
    uint4 bp[4];

    // prologue: stage chunk 0
#pragma unroll
    for (int i = 0; i < 16; i++) {
        int row = xr_row + 8 * i;
        xp[i] = pk4(*(const float4*)(xbase + (size_t)row * 768 + xr_c4 * 4));
    }
#pragma unroll
    for (int g = 0; g < 4; g++) {
        int cc = tid + g * 128, n = cc >> 3, k0 = (cc & 7) * 8;
        bp[g] = pk8(fc1_w + (size_t)n * 768 + k0);
    }
#pragma unroll
    for (int i = 0; i < 16; i++)
        *(uint2*)(A0 + (xr_row + 8 * i) * LDA + xr_c4 * 4) = xp[i];
#pragma unroll
    for (int g = 0; g < 4; g++) ((uint4*)Bb0)[tid + g * 128] = bp[g];
    __syncthreads();

    FragC acc[2][4];
#pragma unroll
    for (int mf = 0; mf < 2; mf++)
#pragma unroll
        for (int nf = 0; nf < 4; nf++) wmma::fill_fragment(acc[mf][nf], 0.0f);

    for (int kb = 0; kb < 12; kb++) {
        __nv_bfloat16* Acur = (kb & 1) ? A1 : A0;
        __nv_bfloat16* Bcur = (kb & 1) ? Bb1 : Bb0;
        __nv_bfloat16* Anxt = (kb & 1) ? A0 : A1;
        __nv_bfloat16* Bnxt = (kb & 1) ? Bb0 : Bb1;

        if (kb < 11) {
#pragma unroll
            for (int i = 0; i < 16; i++) {
                int row = xr_row + 8 * i;
                xp[i] = pk4(*(const float4*)(xbase + (size_t)row * 768 + (kb + 1) * 64 + xr_c4 * 4));
            }
#pragma unroll
            for (int g = 0; g < 4; g++) {
                int cc = tid + g * 128, n = cc >> 3, k0 = (cc & 7) * 8;
                bp[g] = pk8(fc1_w + (size_t)n * 768 + (kb + 1) * 64 + k0);
            }
        } else {
#pragma unroll
            for (int g = 0; g < 4; g++) {
                int cc = tid + g * 128, n = cc >> 3, k0 = (cc & 7) * 8;
                bp[g] = pk8(conv_w + n * 64 + k0);
            }
        }

#pragma unroll
        for (int ks = 0; ks < 4; ks++) {
            FragA a0f, a1f;
            wmma::load_matrix_sync(a0f, Acur + (m0)      * LDA + ks * 16, LDA);
            wmma::load_matrix_sync(a1f, Acur + (m0 + 16) * LDA + ks * 16, LDA);
#pragma unroll
            for (int nf = 0; nf < 4; nf++) {
                FragB bf;
                wmma::load_matrix_sync(bf, Bcur + nf * 16 * 64 + ks * 16, 64);
                wmma::mma_sync(acc[0][nf], a0f, bf, acc[0][nf]);
                wmma::mma_sync(acc[1][nf], a1f, bf, acc[1][nf]);
            }
        }

        if (kb < 11) {
#pragma unroll
            for (int i = 0; i < 16; i++)
                *(uint2*)(Anxt + (xr_row + 8 * i) * LDA + xr_c4 * 4) = xp[i];
#pragma unroll
            for (int g = 0; g < 4; g++) ((uint4*)Bnxt)[tid + g * 128] = bp[g];
        } else {
#pragma unroll
            for (int g = 0; g < 4; g++) ((uint4*)Bb0)[tid + g * 128] = bp[g];
        }
        __syncthreads();
    }

    // epilogue fc1 -> Cf -> (+biasF, bf16) -> A0
#pragma unroll
    for (int mf = 0; mf < 2; mf++)
#pragma unroll
        for (int nf = 0; nf < 4; nf++)
            wmma::store_matrix_sync(Cf + (m0 + mf * 16) * LDC + nf * 16,
                                    acc[mf][nf], LDC, wmma::mem_row_major);
    __syncthreads();
    {
        uint2* d = (uint2*)(A0 + tid * LDA);
#pragma unroll
        for (int g = 0; g < 16; g++) {
            float4 v = *(const float4*)(Cf + tid * LDC + g * 4);
            v.x += biasF[g * 4];     v.y += biasF[g * 4 + 1];
            v.z += biasF[g * 4 + 2]; v.w += biasF[g * 4 + 3];
            d[g] = pk4(v);
        }
    }
    __syncthreads();

    // conv chain
    __nv_bfloat16* cur = A0;
    for (int L = 0; L < 8; L++) {
        __nv_bfloat16* Bcur = (L & 1) ? Bb1 : Bb0;
        __nv_bfloat16* Bnxt = (L & 1) ? Bb0 : Bb1;

        if (L < 7) {
#pragma unroll
            for (int g = 0; g < 4; g++) {
                int cc = tid + g * 128, n = cc >> 3, k0 = (cc & 7) * 8;
                bp[g] = pk8(conv_w + (L + 1) * 4096 + n * 64 + k0);
            }
        }

#pragma unroll
        for (int mf = 0; mf < 2; mf++)
#pragma unroll
            for (int nf = 0; nf < 4; nf++) wmma::fill_fragment(acc[mf][nf], 0.0f);
#pragma unroll
        for (int ks = 0; ks < 4; ks++) {
            FragA a0f, a1f;
            wmma::load_matrix_sync(a0f, cur + (m0)      * LDA + ks * 16, LDA);
            wmma::load_matrix_sync(a1f, cur + (m0 + 16) * LDA + ks * 16, LDA);
#pragma unroll
            for (int nf = 0; nf < 4; nf++) {
                FragB bf;
                wmma::load_matrix_sync(bf, Bcur + nf * 16 * 64 + ks * 16, 64);
                wmma::mma_sync(acc[0][nf], a0f, bf, acc[0][nf]);
                wmma::mma_sync(acc[1][nf], a1f, bf, acc[1][nf]);
            }
        }
#pragma unroll
        for (int mf = 0; mf < 2; mf++)
#pragma unroll
            for (int nf = 0; nf < 4; nf++)
                wmma::store_matrix_sync(Cf + (m0 + mf * 16) * LDC + nf * 16,
                                        acc[mf][nf], LDC, wmma::mem_row_major);
        if (L < 7) {
#pragma unroll
            for (int g = 0; g < 4; g++) ((uint4*)Bnxt)[tid + g * 128] = bp[g];
        }
        __syncthreads();

        if (L < 7) {
            __nv_bfloat16* out = (L & 1) ? A0 : A1;
            const float* bl = biasC + L * 64;
            uint2* d = (uint2*)(out + tid * LDA);
#pragma unroll
            for (int g = 0; g < 16; g++) {
                float4 v = *(const float4*)(Cf + tid * LDC + g * 4);
                v.x += bl[g * 4];     v.y += bl[g * 4 + 1];
                v.z += bl[g * 4 + 2]; v.w += bl[g * 4 + 3];
                d[g] = pk4(v);
            }
            cur = out;
        } else {
            const float* bl = biasC + 7 * 64;
            float* gout = g_G + (size_t)(t0 + tid) * 64;
#pragma unroll
            for (int g = 0; g < 16; g++) {
                float4 v;
                int c = g * 4;
                v.x = gelu_exact(Cf[tid * LDC + c]     + bl[c]     + __bfloat162float(A0[tid * LDA + c]));
                v.y = gelu_exact(Cf[tid * LDC + c + 1] + bl[c + 1] + __bfloat162float(A0[tid * LDA + c + 1]));
                v.z = gelu_exact(Cf[tid * LDC + c + 2] + bl[c + 2] + __bfloat162float(A0[tid * LDA + c + 2]));
                v.w = gelu_exact(Cf[tid * LDC + c + 3] + bl[c + 3] + __bfloat162float(A0[tid * LDA + c + 3]));
                *(float4*)(gout + c) = v;
            }
        }
        __syncthreads();
    }
}

// ---------------------------------------------------------------------------
// K2a: qkv pointwise 64->48, float2-vectorized (unchanged)
// ---------------------------------------------------------------------------
__global__ __launch_bounds__(128) void k_qkv(
    const float* __restrict__ qkv_w, const float* __restrict__ qkv_b)
{
    __shared__ float wq[64 * 48];
    __shared__ float bq[48];
    const int tid = threadIdx.x;
    for (int i = tid; i < 3072; i += 128) {
        int j = i / 64, c = i % 64;
        wq[c * 48 + j] = qkv_w[i];
    }
    if (tid < 48) bq[tid] = qkv_b[tid];
    __syncthreads();

    const int pos = (blockIdx.x * 128 + tid) * 2;
    float2 acc[48];
#pragma unroll
    for (int j = 0; j < 48; j++) { acc[j].x = bq[j]; acc[j].y = bq[j]; }
    for (int c = 0; c < 64; c++) {
        float2 xv = *(const float2*)(g_G + (size_t)c * POSN + pos);
        const float4* wr = (const float4*)(wq + c * 48);
#pragma unroll
        for (int j4 = 0; j4 < 12; j4++) {
            float4 wv = wr[j4];
            acc[j4 * 4 + 0].x += xv.x * wv.x; acc[j4 * 4 + 0].y += xv.y * wv.x;
            acc[j4 * 4 + 1].x += xv.x * wv.y; acc[j4 * 4 + 1].y += xv.y * wv.y;
            acc[j4 * 4 + 2].x += xv.x * wv.z; acc[j4 * 4 + 2].y += xv.y * wv.z;
            acc[j4 * 4 + 3].x += xv.x * wv.w; acc[j4 * 4 + 3].y += xv.y * wv.w;
        }
    }
#pragma unroll
    for (int j = 0; j < 48; j++)
        *(float2*)(g_QKV + (size_t)j * POSN + pos) = acc[j];
}

// ---------------------------------------------------------------------------
// K2b: attention + proj, fused (unchanged)
// ---------------------------------------------------------------------------
#define T_R 260
#define T_CH 780
__global__ __launch_bounds__(256) void k_attn_proj(
    const float* __restrict__ dep1_w, const float* __restrict__ dep_b,
    const float* __restrict__ dep1_b, const float* __restrict__ rpb,
    const float* __restrict__ proj_w, const float* __restrict__ proj_b)
{
    __shared__ float tile[4 * T_CH];
    __shared__ float s_w[162];
    __shared__ float s_b0[18];
    __shared__ float s_b1[18];
    __shared__ float s_r[72];
    __shared__ float wp[16 * 64];
    __shared__ float pb[64];

    const int tid = threadIdx.x;
    if (tid < 162) s_w[tid] = dep1_w[tid];
    if (tid < 18)  s_b0[tid] = dep_b[tid];
    if (tid < 18)  s_b1[tid] = dep1_b[tid];
    if (tid < 72)  s_r[tid] = rpb[tid];
    for (int i = tid; i < 1024; i += 256) {
        int c = i / 16, m = i % 16;
        wp[m * 64 + c] = proj_w[i];
    }
    if (tid < 64) pb[tid] = proj_b[tid];

    const int hh = blockIdx.x >> 3;
    const int w0 = (blockIdx.x & 7) * 256;
    const int pos = hh * 2048 + w0 + tid;
    const int tc = tid + 1;

    float o[16];

    for (int n = 0; n < 8; n++) {
        __syncthreads();
        for (int i = tid; i < 4 * 774; i += 256) {
            int ch = i / 774, rem = i % 774;
            int r = rem / 258, c = rem % 258;
            int hr = hh - 1 + r, wc = w0 - 1 + c;
            float v = 0.f;
            if ((unsigned)hr < 32u && (unsigned)wc < 2048u)
                v = g_QKV[(size_t)(6 * n + 2 + ch) * POSN + hr * 2048 + wc];
            tile[ch * T_CH + r * T_R + c] = v;
        }
        __syncthreads();

        float q0 = g_QKV[(size_t)(6 * n)     * POSN + pos];
        float q1 = g_QKV[(size_t)(6 * n + 1) * POSN + pos];

        float kin[2][9];
#pragma unroll
        for (int d = 0; d < 9; d++) {
            int r = d / 3, dw = d % 3 - 1;
            kin[0][d] = tile[0 * T_CH + r * T_R + tc + dw];
            kin[1][d] = tile[1 * T_CH + r * T_R + tc + dw];
        }
        float lg[9];
#pragma unroll
        for (int s = 0; s < 9; s++) {
            float k0 = kin[0][s], k1 = kin[1][s];
#pragma unroll
            for (int d = 0; d < 9; d++) {
                k0 += s_w[s * 9 + d]       * kin[0][d];
                k1 += s_w[(9 + s) * 9 + d] * kin[1][d];
            }
            k0 += s_b0[s]     + s_b1[s];
            k1 += s_b0[9 + s] + s_b1[9 + s];
            float r = s_r[n * 9 + s];
            lg[s] = SCALE * (q0 * k0 + q1 * k1 + (q0 + q1) * r);
        }
        float mx = lg[0];
#pragma unroll
        for (int s = 1; s < 9; s++) mx = fmaxf(mx, lg[s]);
        float att[9], sum = 0.f;
#pragma unroll
        for (int s = 0; s < 9; s++) { att[s] = __expf(lg[s] - mx); sum += att[s]; }
        float inv = 1.f / sum;

        float vin[2][9];
#pragma unroll
        for (int d = 0; d < 9; d++) {
            int r = d / 3, dw = d % 3 - 1;
            vin[0][d] = tile[2 * T_CH + r * T_R + tc + dw];
            vin[1][d] = tile[3 * T_CH + r * T_R + tc + dw];
        }
        float o0 = 0.f, o1 = 0.f;
#pragma unroll
        for (int s = 0; s < 9; s++) {
            float v0 = vin[0][s], v1 = vin[1][s];
#pragma unroll
            for (int d = 0; d < 9; d++) {
                v0 += s_w[s * 9 + d]       * vin[0][d];
                v1 += s_w[(9 + s) * 9 + d] * vin[1][d];
            }
            v0 += s_b0[s]     + s_b1[s];
            v1 += s_b0[9 + s] + s_b1[9 + s];
            o0 += att[s] * v0;
            o1 += att[s] * v1;
        }
        o[2 * n]     = o0 * inv;
        o[2 * n + 1] = o1 * inv;
    }

#pragma unroll 4
    for (int c = 0; c < 64; c++) {
        float s = pb[c];
#pragma unroll
        for (int m = 0; m < 16; m++) s += o[m] * wp[m * 64 + c];
        g_Pb[(size_t)c * POSN + pos] = __float2bfloat16(s);
    }
}

// ---------------------------------------------------------------------------
// K3: fc2 (64->768) bf16 wmma, direct-gmem C, RESTRUCTURED for latency hiding:
//   - all 8 x-fragment loads front-batched per chunk (MLP ~8/warp)
//   - A fragments reloaded from resident SMEM per K-step (frees 64 regs,
//     keeps kernel <=128 regs for 2 CTA/SM with no spills)
//   - ks-outer / nf-inner MMA loop; y stores batched at end (no stall)
// 256 tokens/CTA, 8 warps, 256 CTAs. One sync per chunk.
// SMEM: Abuf bf16[256][80] 40960 @0 ; Bb0 8192 @40960 ; Bb1 8192 @49152 ;
//       ones 512 @57344 ; bias tiles 2x2048 @57856  -> total 61952
// ---------------------------------------------------------------------------
__global__ __launch_bounds__(256, 2) void k3_mma(
    const float* __restrict__ x, const float* __restrict__ fc2_w,
    const float* __restrict__ fc2_b, float* __restrict__ y)
{
    extern __shared__ char sm[];
    __nv_bfloat16* Abuf  = (__nv_bfloat16*)sm;
    __nv_bfloat16* Bb0   = (__nv_bfloat16*)(sm + 40960);
    __nv_bfloat16* Bb1   = (__nv_bfloat16*)(sm + 49152);
    __nv_bfloat16* Bones = (__nv_bfloat16*)(sm + 57344);   // 16x16 row-major, col0 = 1
    __nv_bfloat16* Bbi0  = (__nv_bfloat16*)(sm + 57856);   // 4 col-major 16x16 tiles
    __nv_bfloat16* Bbi1  = (__nv_bfloat16*)(sm + 59904);

    const int tid = threadIdx.x;
    const int wid = tid >> 5;
    const int t0  = blockIdx.x * 256;
    const int m0  = wid * 32;

    uint4 bp[2];
    float bnext = 0.f;

    // init ones tile + zero bias tiles
    {
        int r = tid >> 4, c = tid & 15;
        Bones[r * 16 + c] = __float2bfloat16(c == 0 ? 1.f : 0.f);
        ((uint4*)Bbi0)[tid & 127] = make_uint4(0, 0, 0, 0);
        ((uint4*)Bbi1)[tid & 127] = make_uint4(0, 0, 0, 0);
    }

    // stage A (bf16 rows from g_Pb), first B chunk, first bias
    {
        const uint4* s = (const uint4*)(g_Pb + (size_t)(t0 + tid) * 64);
        uint4* d = (uint4*)(Abuf + tid * LDA);
#pragma unroll
        for (int g = 0; g < 8; g++) d[g] = s[g];
    }
#pragma unroll
    for (int g = 0; g < 2; g++) {
        int cc = tid + g * 256, n = cc >> 3, k0 = (cc & 7) * 8;
        bp[g] = pk8(fc2_w + (size_t)n * 64 + k0);
    }
#pragma unroll
    for (int g = 0; g < 2; g++) ((uint4*)Bb0)[tid + g * 256] = bp[g];
    if (tid < 64)
        Bbi0[(tid >> 4) * 256 + (tid & 15) * 16] = __float2bfloat16(fc2_b[tid]);
    __syncthreads();

    FragA ones_f;
    wmma::load_matrix_sync(ones_f, Bones, 16);

    for (int nb = 0; nb < 12; nb++) {
        __nv_bfloat16* Bcur  = (nb & 1) ? Bb1 : Bb0;
        __nv_bfloat16* Bnxt  = (nb & 1) ? Bb0 : Bb1;
        __nv_bfloat16* BbiC  = (nb & 1) ? Bbi1 : Bbi0;
        __nv_bfloat16* BbiN  = (nb & 1) ? Bbi0 : Bbi1;

        // prefetch next B chunk + bias into registers
        if (nb < 11) {
#pragma unroll
            for (int g = 0; g < 2; g++) {
                int cc = tid + g * 256, n = cc >> 3, k0 = (cc & 7) * 8;
                bp[g] = pk8(fc2_w + (size_t)((nb + 1) * 64 + n) * 64 + k0);
            }
            if (tid < 64) bnext = fc2_b[(nb + 1) * 64 + tid];
        }

        // 1) front-batch ALL 8 x-fragment loads (residual folded into acc)
        FragC acc[2][4];
#pragma unroll
        for (int mf = 0; mf < 2; mf++)
#pragma unroll
            for (int nf = 0; nf < 4; nf++)
                wmma::load_matrix_sync(acc[mf][nf],
                    x + (size_t)(t0 + m0 + mf * 16) * 768 + nb * 64 + nf * 16,
                    768, wmma::mem_row_major);

        // 2) bias via ones-MMA
#pragma unroll
        for (int nf = 0; nf < 4; nf++) {
            FragB biasf;
            wmma::load_matrix_sync(biasf, BbiC + nf * 256, 16);
            wmma::mma_sync(acc[0][nf], ones_f, biasf, acc[0][nf]);
            wmma::mma_sync(acc[1][nf], ones_f, biasf, acc[1][nf]);
        }

        // 3) main MMAs: A from resident SMEM, once per K-step
#pragma unroll
        for (int ks = 0; ks < 4; ks++) {
            FragA a0, a1;
            wmma::load_matrix_sync(a0, Abuf + (m0)      * LDA + ks * 16, LDA);
            wmma::load_matrix_sync(a1, Abuf + (m0 + 16) * LDA + ks * 16, LDA);
#pragma unroll
            for (int nf = 0; nf < 4; nf++) {
                FragB bf;
                wmma::load_matrix_sync(bf, Bcur + nf * 16 * 64 + ks * 16, 64);
                wmma::mma_sync(acc[0][nf], a0, bf, acc[0][nf]);
                wmma::mma_sync(acc[1][nf], a1, bf, acc[1][nf]);
            }
        }

        // 4) batched y stores (fire-and-forget)
#pragma unroll
        for (int mf = 0; mf < 2; mf++)
#pragma unroll
            for (int nf = 0; nf < 4; nf++)
                wmma::store_matrix_sync(
                    y + (size_t)(t0 + m0 + mf * 16) * 768 + nb * 64 + nf * 16,
                    acc[mf][nf], 768, wmma::mem_row_major);

        // 5) stage next B + bias, one sync
        if (nb < 11) {
#pragma unroll
            for (int g = 0; g < 2; g++) ((uint4*)Bnxt)[tid + g * 256] = bp[g];
            if (tid < 64)
                BbiN[(tid >> 4) * 256 + (tid & 15) * 16] = __float2bfloat16(bnext);
            __syncthreads();
        }
    }
}

// ---------------------------------------------------------------------------
extern "C" void kernel_launch(void* const* d_in, const int* in_sizes, int n_in,
                              void* d_out, int out_size)
{
    const float* x      = (const float*)d_in[0];
    const float* fc1_w  = (const float*)d_in[1];
    const float* fc1_b  = (const float*)d_in[2];
    const float* conv_w = (const float*)d_in[3];
    const float* conv_b = (const float*)d_in[4];
    const float* qkv_w  = (const float*)d_in[5];
    const float* qkv_b  = (const float*)d_in[6];
    const float* dep1_w = (const float*)d_in[7];
    const float* dep_b  = (const float*)d_in[8];
    const float* dep1_b = (const float*)d_in[9];
    const float* rpb    = (const float*)d_in[10];
    const float* proj_w = (const float*)d_in[11];
    const float* proj_b = (const float*)d_in[12];
    const float* fc2_w  = (const float*)d_in[13];
    const float* fc2_b  = (const float*)d_in[14];
    float* y = (float*)d_out;

    cudaFuncSetAttribute(k1_mma, cudaFuncAttributeMaxDynamicSharedMemorySize, 96512);
    cudaFuncSetAttribute(k3_mma, cudaFuncAttributeMaxDynamicSharedMemorySize, 61952);

    k1_mma<<<512, 128, 96512>>>(x, fc1_w, fc1_b, conv_w, conv_b);
    k_qkv <<<256, 128>>>(qkv_w, qkv_b);
    k_attn_proj<<<256, 256>>>(dep1_w, dep_b, dep1_b, rpb, proj_w, proj_b);
    k3_mma<<<256, 256, 61952>>>(x, fc2_w, fc2_b, y);
}